// round 16
// baseline (speedup 1.0000x reference)
#include <cuda_runtime.h>
#include <cuda_bf16.h>

// Problem dims
#define B_    512
#define T_    1024
#define DIN_  64
#define H_    256
#define MLPH_ 256
#define DOUT_ 64

// ---------------- LSTM config ----------------
// 32 groups x 16 batch rows; 8 CTAs per group-pair; physical CTA (g,q) serves
// groups 2g and 2g+1 in alternating phases (barrier latency hidden by the
// other group's GEMM). 256 threads = 8 warps: ks = wid>>2 (K-half), ng = wid&3.
// Warp tile m16 x n32 x K160. Plane-major fragment layout (conflict-free).
#define ABUF0 40960              // A frags group 2g:   20 blk x 256 u32
#define ABUF1 46080              // A frags group 2g+1
#define REDO  51200              // 2048 f32 reduction buffer
#define LSTM_SMEM_BYTES (53248 * 4)   // 212992

// ---------------- MLP config (proven R14) ----------------
#define MW_OFF 16384
#define W2_OFF 32768
#define MLP_SMEM_BYTES (49152 * 4)    // 196608

// Device scratch (static; cudaMalloc forbidden)
__device__ float    g_hs[(size_t)B_ * T_ * H_];          // hidden states (MLP input)
__device__ unsigned g_hfrag[2][32][16][256];             // h frags, double-buffered
__device__ unsigned g_xfrag[(size_t)T_ * 32 * 4 * 256];  // x frags (all t)
__device__ unsigned g_bar[32];

__device__ __forceinline__ float sigf(float v) {
    return __fdividef(1.0f, 1.0f + __expf(-v));
}
__device__ __forceinline__ float tfast(float v) {
    float e = __expf(-2.0f * fabsf(v));
    return copysignf(__fdividef(1.0f - e, 1.0f + e), v);
}

__device__ __forceinline__ void mma16816(float* c, const unsigned* a, const unsigned* b) {
    asm volatile(
        "mma.sync.aligned.m16n8k16.row.col.f32.bf16.bf16.f32 "
        "{%0,%1,%2,%3},{%4,%5,%6,%7},{%8,%9},{%0,%1,%2,%3};\n"
        : "+f"(c[0]), "+f"(c[1]), "+f"(c[2]), "+f"(c[3])
        : "r"(a[0]), "r"(a[1]), "r"(a[2]), "r"(a[3]), "r"(b[0]), "r"(b[1]));
}

__device__ __forceinline__ void split_pack(float2 v, unsigned& uhi, unsigned& ulo) {
    __nv_bfloat16 hx = __float2bfloat16(v.x);
    __nv_bfloat16 hy = __float2bfloat16(v.y);
    __nv_bfloat16 lx = __float2bfloat16(v.x - __bfloat162float(hx));
    __nv_bfloat16 ly = __float2bfloat16(v.y - __bfloat162float(hy));
    uhi = (unsigned)__bfloat16_as_ushort(hx) | ((unsigned)__bfloat16_as_ushort(hy) << 16);
    ulo = (unsigned)__bfloat16_as_ushort(lx) | ((unsigned)__bfloat16_as_ushort(ly) << 16);
}

// ---------------------------------------------------------------------------
// init: pack h0 into fragment layout (phase 0) for all 32 groups, reset bars.
// 16384 threads: (g 5b, blk 4b, ln 5b).
// ---------------------------------------------------------------------------
__global__ void init_kernel(const float* __restrict__ h0) {
    unsigned s = blockIdx.x * 256 + threadIdx.x;   // 0..16383
    int ln = s & 31, blk = (s >> 5) & 15, g = (s >> 9) & 31;
    unsigned hi[4], lo[4];
#pragma unroll
    for (int r = 0; r < 4; r++) {
        int row = g * 16 + (ln >> 2) + (r & 1) * 8;
        int un  = blk * 16 + (ln & 3) * 2 + (r >> 1) * 8;
        float2 v = *(const float2*)&h0[(size_t)row * H_ + un];
        split_pack(v, hi[r], lo[r]);
    }
    unsigned* dst = &g_hfrag[0][g][blk][ln * 4];
    *(uint4*)dst         = make_uint4(hi[0], hi[1], hi[2], hi[3]);
    *(uint4*)(dst + 128) = make_uint4(lo[0], lo[1], lo[2], lo[3]);
    if (s < 32) g_bar[s] = 0u;
}

// ---------------------------------------------------------------------------
// xfrag: pack x for ALL timesteps. grid 16384 x 256: (t 10b, g 5b, xk 2b, ln 5b)
// ---------------------------------------------------------------------------
__global__ void xfrag_kernel(const float* __restrict__ x) {
    unsigned s = blockIdx.x * 256 + threadIdx.x;
    int ln = s & 31, xk = (s >> 5) & 3, g = (s >> 7) & 31, t = s >> 12;
    unsigned hi[4], lo[4];
#pragma unroll
    for (int r = 0; r < 4; r++) {
        int row = g * 16 + (ln >> 2) + (r & 1) * 8;
        int kb  = xk * 16 + (ln & 3) * 2 + (r >> 1) * 8;     // 0..63
        float2 v = *(const float2*)&x[((size_t)row * T_ + t) * DIN_ + kb];
        split_pack(v, hi[r], lo[r]);
    }
    unsigned* dst = g_xfrag + ((((size_t)t * 32 + g) * 4 + xk) << 8) + ln * 4;
    *(uint4*)dst         = make_uint4(hi[0], hi[1], hi[2], hi[3]);
    *(uint4*)(dst + 128) = make_uint4(lo[0], lo[1], lo[2], lo[3]);
}

// ---------------------------------------------------------------------------
// Persistent LSTM, group-interleaved. grid 128, 256 threads.
// ---------------------------------------------------------------------------
#define LOADFRAG(kt, bf) do {                                                  \
    const unsigned* _a = smU + curbuf + (kt) * 256 + lane * 4;                 \
    *(uint4*)(ah[bf]) = *(const uint4*)(_a);                                   \
    *(uint4*)(al[bf]) = *(const uint4*)(_a + 128);                             \
    const unsigned* _b = smU + ((kt) * 4 + ng) * 512 + lane * 4;               \
    *(uint4*)(bh[bf])     = *(const uint4*)(_b);                               \
    *(uint4*)(bh[bf] + 4) = *(const uint4*)(_b + 128);                         \
    *(uint4*)(bl[bf])     = *(const uint4*)(_b + 256);                         \
    *(uint4*)(bl[bf] + 4) = *(const uint4*)(_b + 384);                         \
} while (0)

#define MMASTEP(bf) do {                                                       \
    _Pragma("unroll")                                                          \
    for (int j = 0; j < 4; j++) {                                              \
        mma16816(acc[j], ah[bf], bh[bf] + j * 2);                              \
        mma16816(acc[j], ah[bf], bl[bf] + j * 2);                              \
        mma16816(acc[j], al[bf], bh[bf] + j * 2);                              \
    }                                                                          \
} while (0)

__global__ void __launch_bounds__(256, 1) lstm_kernel(
    const float* __restrict__ c0,   const float* __restrict__ W_ih,
    const float* __restrict__ W_hh, const float* __restrict__ b_ih,
    const float* __restrict__ b_hh)
{
    extern __shared__ unsigned smU[];
    float* redf = (float*)(smU + REDO);

    const int tid  = threadIdx.x;
    const int g    = blockIdx.x >> 3;    // group-pair 0..15
    const int q    = blockIdx.x & 7;     // unit CTA   0..7
    const int u0   = q * 32;
    const int lane = tid & 31;
    const int wid  = tid >> 5;
    const int ks   = wid >> 2;           // K-half 0..1
    const int ng   = wid & 3;            // n-group 0..3 (32 gate cols)
    const int gid  = lane >> 2;
    const int tg   = lane & 3;
    const int rc   = ng * 32 + lane;

    // ---- one-time: fragment-pack weight slice (hi+lo, plane-major) ----
    for (int s = tid; s < 20480; s += 256) {
        int w  = s & 7;
        int ln = (s >> 3) & 31;
        int bb = s >> 8;                 // kt*4 + bng
        int j = w >> 1, r = w & 1;
        int bng = bb & 3, kt = bb >> 2;
        int grow = j * H_ + u0 + bng * 8 + (ln >> 2);
        int k    = kt * 16 + (ln & 3) * 2 + r * 8;
        float2 wv = (k < H_) ? *(const float2*)&W_hh[(size_t)grow * H_ + k]
                             : *(const float2*)&W_ih[(size_t)grow * DIN_ + (k - H_)];
        unsigned uhi, ulo;
        split_pack(wv, uhi, ulo);
        int a = bb * 512 + (w >> 2) * 128 + ln * 4 + (w & 3);
        smU[a]       = uhi;
        smU[a + 256] = ulo;
    }

    // bias (ks0 seeds acc; ks1 seeds 0) + cell states for both groups (ks0)
    float bs[4][2];
#pragma unroll
    for (int j = 0; j < 4; j++)
#pragma unroll
        for (int e = 0; e < 2; e++) {
            int un = u0 + ng * 8 + tg * 2 + e;
            bs[j][e] = (ks == 0) ? (b_ih[j * H_ + un] + b_hh[j * H_ + un]) : 0.0f;
        }
    float cst[2][4];
#pragma unroll
    for (int p2 = 0; p2 < 2; p2++)
#pragma unroll
        for (int rr = 0; rr < 4; rr++) cst[p2][rr] = 0.0f;
    if (ks == 0) {
#pragma unroll
        for (int p2 = 0; p2 < 2; p2++)
#pragma unroll
            for (int rr = 0; rr < 4; rr++) {
                int row = g * 32 + p2 * 16 + gid + (rr >> 1) * 8;
                int un  = u0 + ng * 8 + tg * 2 + (rr & 1);
                cst[p2][rr] = c0[(size_t)row * H_ + un];
            }
    }
    __syncthreads();

    // ---- prologue: stage group 2g, t=0 into ABUF0 ----
    {
        const uint4* hs = (const uint4*)&g_hfrag[0][2 * g][0][0];
        const uint4* xs = (const uint4*)(g_xfrag + ((size_t)(2 * g) << 10));
        for (int i4 = tid; i4 < 1280; i4 += 256) {
            uint4 v = (i4 < 1024) ? __ldcg(hs + i4) : __ldcg(xs + (i4 - 1024));
            *(uint4*)&smU[ABUF0 + i4 * 4] = v;
        }
    }
    __syncthreads();

    const int k0   = ks * 10;
    const int ucol = u0 + ng * 8 + tg * 2;

    for (int t = 0; t < T_; t++) {
#pragma unroll
        for (int ph = 0; ph < 2; ph++) {
            const int curg = 2 * g + ph;
            const int pg   = 2 * g + (ph ^ 1);
            const int pt   = t + ph;                 // prefetch timestep
            const unsigned curbuf = ph ? (unsigned)ABUF1 : (unsigned)ABUF0;
            const unsigned pbuf   = ph ? (unsigned)ABUF0 : (unsigned)ABUF1;
            const bool dopf = (pt < T_);

            // wait for prefetch-group barrier (usually already satisfied)
            if (dopf && pt > 0 && tid == 0) {
                unsigned tgt = 8u * (unsigned)pt, v;
                do {
                    asm volatile("ld.global.acquire.gpu.u32 %0, [%1];"
                                 : "=r"(v) : "l"(g_bar + pg));
                } while (v < tgt);
            }
            __syncthreads();

            // issue prefetch LDGs (land in regs during GEMM)
            uint4 ph4[4], px4;
            if (dopf) {
                const uint4* hs = (const uint4*)&g_hfrag[pt & 1][pg][0][0];
#pragma unroll
                for (int jj = 0; jj < 4; jj++) ph4[jj] = __ldcg(hs + tid + jj * 256);
                const uint4* xs = (const uint4*)(g_xfrag + (((size_t)pt * 32 + pg) << 10));
                px4 = __ldcg(xs + tid);
            }

            // ---- GEMM: this warp's K-half, 3-pass bf16 split ----
            float acc[4][4];
#pragma unroll
            for (int j = 0; j < 4; j++)
#pragma unroll
                for (int rr = 0; rr < 4; rr++) acc[j][rr] = bs[j][rr & 1];

            unsigned ah[2][4], al[2][4], bh[2][8], bl[2][8];
            LOADFRAG(k0, 0);
#pragma unroll 2
            for (int kk = 0; kk < 10; kk++) {
                int bf = kk & 1;
                if (kk + 1 < 10) LOADFRAG(k0 + kk + 1, bf ^ 1);
                MMASTEP(bf);
            }

            // ---- K-split reduction ----
            if (ks == 1) {
#pragma unroll
                for (int j = 0; j < 4; j++)
#pragma unroll
                    for (int rr = 0; rr < 4; rr++)
                        redf[(j * 4 + rr) * 128 + rc] = acc[j][rr];
            }
            __syncthreads();

            float hv[4];
            if (ks == 0) {
#pragma unroll
                for (int j = 0; j < 4; j++)
#pragma unroll
                    for (int rr = 0; rr < 4; rr++)
                        acc[j][rr] += redf[(j * 4 + rr) * 128 + rc];

                // pointwise LSTM cell
#pragma unroll
                for (int rr = 0; rr < 4; rr++) {
                    float ig = sigf(acc[0][rr]);
                    float fg = sigf(acc[1][rr]);
                    float gg = tfast(acc[2][rr]);
                    float og = sigf(acc[3][rr]);
                    float cn = fmaf(fg, cst[ph][rr], ig * gg);
                    cst[ph][rr] = cn;
                    hv[rr] = og * tfast(cn);
                }
                // h -> fragment layout in global
                int nb  = (t + 1) & 1;
                int blk = 2 * q + (ng >> 1);
#pragma unroll
                for (int s = 0; s < 2; s++) {
                    unsigned uhi, ulo;
                    split_pack(make_float2(hv[s * 2], hv[s * 2 + 1]), uhi, ulo);
                    int rA = s | ((ng & 1) << 1);
                    unsigned* d = &g_hfrag[nb][curg][blk][lane * 4 + rA];
                    d[0]   = uhi;
                    d[128] = ulo;
                }
            }

            // ---- commit prefetch to the other group's A buffer ----
            if (dopf) {
#pragma unroll
                for (int jj = 0; jj < 4; jj++)
                    *(uint4*)&smU[pbuf + (tid + jj * 256) * 4] = ph4[jj];
                *(uint4*)&smU[pbuf + (1024 + tid) * 4] = px4;
            }

            // ---- release ----
            __syncthreads();
            if (tid == 0)
                asm volatile("red.release.gpu.global.add.u32 [%0], %1;"
                             :: "l"(g_bar + curg), "r"(1u) : "memory");

            // ---- g_hs writeout (off critical path) ----
            if (ks == 0) {
                int row = curg * 16 + gid;
                *(float2*)&g_hs[((size_t)row * T_ + t) * H_ + ucol] =
                    make_float2(hv[0], hv[1]);
                *(float2*)&g_hs[((size_t)(row + 8) * T_ + t) * H_ + ucol] =
                    make_float2(hv[2], hv[3]);
            }
        }
    }
}

// ---------------------------------------------------------------------------
// MLP with bf16x3 tensor cores (proven R14): y = relu(hs@W1^T+b1)@W2^T+b2, *mask
// ---------------------------------------------------------------------------
__global__ void __launch_bounds__(512, 1) mlp_kernel(
    const float* __restrict__ W1, const float* __restrict__ b1,
    const float* __restrict__ W2, const float* __restrict__ b2,
    const float* __restrict__ mask, float* __restrict__ out)
{
    extern __shared__ unsigned smU[];

    const int tid  = threadIdx.x;
    const int lane = tid & 31;
    const int wid  = tid >> 5;
    const int gid  = lane >> 2;
    const int tg   = lane & 3;
    const int mw   = wid & 7;
    const int nh   = wid >> 3;
    const size_t row0 = (size_t)blockIdx.x * 128;

    float acc[4][4][4];
#pragma unroll
    for (int bg = 0; bg < 4; bg++)
#pragma unroll
        for (int j = 0; j < 4; j++)
#pragma unroll
            for (int rr = 0; rr < 4; rr++) acc[bg][j][rr] = 0.0f;

    for (int c = 0; c < 2; c++) {
        for (int s = tid; s < 8192; s += 512) {
            int r = s & 3, ln = (s >> 2) & 31, ab = s >> 7;
            int mt = ab & 7, kt = ab >> 3;
            size_t row = row0 + mt * 16 + (ln >> 2) + (r & 1) * 8;
            int k = c * 128 + kt * 16 + (ln & 3) * 2 + (r >> 1) * 8;
            float2 v = *(const float2*)&g_hs[row * H_ + k];
            unsigned uhi, ulo;
            split_pack(v, uhi, ulo);
            smU[ab * 256 + ln * 4 + r]       = uhi;
            smU[ab * 256 + 128 + ln * 4 + r] = ulo;
        }
        for (int s = tid; s < 16384; s += 512) {
            int w = s & 7, ln = (s >> 3) & 31, wb = s >> 8;
            int bg = wb & 7, kt = wb >> 3;
            int n = bg * 32 + (w >> 1) * 8 + (ln >> 2);
            int k = c * 128 + kt * 16 + (ln & 3) * 2 + (w & 1) * 8;
            float2 v = *(const float2*)&W1[(size_t)n * H_ + k];
            unsigned uhi, ulo;
            split_pack(v, uhi, ulo);
            int a = MW_OFF + wb * 512 + (w >> 2) * 128 + ln * 4 + (w & 3);
            smU[a]       = uhi;
            smU[a + 256] = ulo;
        }
        __syncthreads();

        for (int kt = 0; kt < 8; kt++) {
            const unsigned* _a = smU + (kt * 8 + mw) * 256 + lane * 4;
            unsigned ah[4], al[4];
            *(uint4*)ah = *(const uint4*)_a;
            *(uint4*)al = *(const uint4*)(_a + 128);
#pragma unroll
            for (int bg = 0; bg < 4; bg++) {
                const unsigned* _b = smU + MW_OFF + (kt * 8 + nh * 4 + bg) * 512 + lane * 4;
                unsigned bh[8], bl[8];
                *(uint4*)(bh)     = *(const uint4*)(_b);
                *(uint4*)(bh + 4) = *(const uint4*)(_b + 128);
                *(uint4*)(bl)     = *(const uint4*)(_b + 256);
                *(uint4*)(bl + 4) = *(const uint4*)(_b + 384);
#pragma unroll
                for (int j = 0; j < 4; j++) {
                    mma16816(acc[bg][j], ah, bh + j * 2);
                    mma16816(acc[bg][j], ah, bl + j * 2);
                    mma16816(acc[bg][j], al, bh + j * 2);
                }
            }
        }
        __syncthreads();
    }

    for (int s = tid; s < 8192; s += 512) {
        int w = s & 7, ln = (s >> 3) & 31, wb = s >> 8;
        int bg2 = wb & 1, kt2 = wb >> 1;
        int n = bg2 * 32 + (w >> 1) * 8 + (ln >> 2);
        int k = kt2 * 16 + (ln & 3) * 2 + (w & 1) * 8;
        float2 v = *(const float2*)&W2[(size_t)n * MLPH_ + k];
        unsigned uhi, ulo;
        split_pack(v, uhi, ulo);
        int a = W2_OFF + wb * 512 + (w >> 2) * 128 + ln * 4 + (w & 3);
        smU[a]       = uhi;
        smU[a + 256] = ulo;
    }

#pragma unroll
    for (int bg = 0; bg < 4; bg++)
#pragma unroll
        for (int j = 0; j < 4; j++) {
            int bgp = nh * 4 + bg;
            int colb = bgp * 32 + j * 8 + tg * 2;
            float ba = b1[colb], bbv = b1[colb + 1];
            float v00 = fmaxf(acc[bg][j][0] + ba, 0.0f);
            float v01 = fmaxf(acc[bg][j][1] + bbv, 0.0f);
            float v10 = fmaxf(acc[bg][j][2] + ba, 0.0f);
            float v11 = fmaxf(acc[bg][j][3] + bbv, 0.0f);
            int yb = (bgp * 2 + (j >> 1)) * 8 + mw;
            int rb = (j & 1) * 2;
            unsigned uhi, ulo;
            split_pack(make_float2(v00, v01), uhi, ulo);
            smU[yb * 256 + lane * 4 + rb]       = uhi;
            smU[yb * 256 + 128 + lane * 4 + rb] = ulo;
            split_pack(make_float2(v10, v11), uhi, ulo);
            smU[yb * 256 + lane * 4 + rb + 1]       = uhi;
            smU[yb * 256 + 128 + lane * 4 + rb + 1] = ulo;
        }
    __syncthreads();

    float acc2[4][4];
#pragma unroll
    for (int j = 0; j < 4; j++)
#pragma unroll
        for (int rr = 0; rr < 4; rr++) acc2[j][rr] = 0.0f;

    for (int kt2 = 0; kt2 < 16; kt2++) {
        const unsigned* _a = smU + (kt2 * 8 + mw) * 256 + lane * 4;
        unsigned ah[4], al[4];
        *(uint4*)ah = *(const uint4*)_a;
        *(uint4*)al = *(const uint4*)(_a + 128);
        const unsigned* _b = smU + W2_OFF + (kt2 * 2 + nh) * 512 + lane * 4;
        unsigned bh[8], bl[8];
        *(uint4*)(bh)     = *(const uint4*)(_b);
        *(uint4*)(bh + 4) = *(const uint4*)(_b + 128);
        *(uint4*)(bl)     = *(const uint4*)(_b + 256);
        *(uint4*)(bl + 4) = *(const uint4*)(_b + 384);
#pragma unroll
        for (int j = 0; j < 4; j++) {
            mma16816(acc2[j], ah, bh + j * 2);
            mma16816(acc2[j], ah, bl + j * 2);
            mma16816(acc2[j], al, bh + j * 2);
        }
    }

    size_t r0 = row0 + mw * 16 + gid;
    size_t r1 = r0 + 8;
    float m0 = mask[r0], m1 = mask[r1];
#pragma unroll
    for (int j = 0; j < 4; j++) {
        int col = nh * 32 + j * 8 + tg * 2;
        float bb0 = b2[col], bb1 = b2[col + 1];
        *(float2*)&out[r0 * DOUT_ + col] =
            make_float2((acc2[j][0] + bb0) * m0, (acc2[j][1] + bb1) * m0);
        *(float2*)&out[r1 * DOUT_ + col] =
            make_float2((acc2[j][2] + bb0) * m1, (acc2[j][3] + bb1) * m1);
    }
}

// ---------------------------------------------------------------------------
extern "C" void kernel_launch(void* const* d_in, const int* in_sizes, int n_in,
                              void* d_out, int out_size) {
    const float* x    = (const float*)d_in[0];
    const float* mask = (const float*)d_in[1];
    const float* h0   = (const float*)d_in[2];
    const float* c0   = (const float*)d_in[3];
    const float* W_ih = (const float*)d_in[4];
    const float* W_hh = (const float*)d_in[5];
    const float* b_ih = (const float*)d_in[6];
    const float* b_hh = (const float*)d_in[7];
    const float* W1   = (const float*)d_in[8];
    const float* b1   = (const float*)d_in[9];
    const float* W2   = (const float*)d_in[10];
    const float* b2   = (const float*)d_in[11];
    float* out = (float*)d_out;

    cudaFuncSetAttribute(lstm_kernel, cudaFuncAttributeMaxDynamicSharedMemorySize,
                         LSTM_SMEM_BYTES);
    cudaFuncSetAttribute(mlp_kernel, cudaFuncAttributeMaxDynamicSharedMemorySize,
                         MLP_SMEM_BYTES);

    init_kernel<<<64, 256>>>(h0);
    xfrag_kernel<<<16384, 256>>>(x);
    lstm_kernel<<<128, 256, LSTM_SMEM_BYTES>>>(c0, W_ih, W_hh, b_ih, b_hh);
    mlp_kernel<<<(B_ * T_) / 128, 512, MLP_SMEM_BYTES>>>(W1, b1, W2, b2, mask, out);
}